// round 8
// baseline (speedup 1.0000x reference)
#include <cuda_runtime.h>
#include <math.h>
#include <stdint.h>

#define NTOK 16384
#define DM   2048
#define NE   64
#define CAP  640
#define BT   128
#define KB   16
#define NCHUNK (DM / KB)   // 128

#define FMA2(c, a, b) \
    asm("fma.rn.f32x2 %0, %1, %2, %0;" : "+l"(c) : "l"(a), "l"(b))

// ---------------- device scratch (zero-initialized; reset by tail kernel) ----------------
__device__ int   g_e12[NTOK];
__device__ float g_w12[2 * NTOK];
__device__ int   g_cnt1[NE];
__device__ float g_counts[NE];
__device__ float g_zsum;
__device__ int   g_done;

// smem float offsets (dynamic)
#define XSOFF 0                      // [2][KB][BT]  = 4096 floats
#define WSOFF (2 * KB * BT)          // [2][KB][128] duplicated = 4096 floats
#define LSTR  68
#define SMEM_FLOATS (BT * LSTR)      // 8704 floats = 34816 B (>= 8192 GEMM floats)

// ---------------- stage A: FFMA2 GEMM (8 tok x 8 exp per thread) + fused epilogue ----------------
__global__ __launch_bounds__(128) void gemm_router(
    const float* __restrict__ x, const float* __restrict__ W,
    float* __restrict__ out_rw)
{
    extern __shared__ float sf[];
    float* xs = sf + XSOFF;
    float* ws = sf + WSOFF;          // duplicated: [k][2e]=[k][2e+1]=W[e][k]
    float* ls = sf;                  // epilogue alias
    __shared__ float zred[4];

    const int tid = threadIdx.x;
    const int tg  = tid & 15;        // 8 tokens = 4 packed pairs
    const int eg  = tid >> 4;        // 8 experts
    const int bt0 = blockIdx.x * BT;

    uint64_t acc[4][8];              // [token-pair][expert] packed f32x2
#pragma unroll
    for (int p = 0; p < 4; p++)
#pragma unroll
        for (int j = 0; j < 8; j++) acc[p][j] = 0ull;

    // ---- load chunk 0 ----
#pragma unroll
    for (int i = 0; i < 4; i++) {
        int idx = i * 128 + tid;
        int t = idx >> 2, kq = idx & 3;
        float4 v = *reinterpret_cast<const float4*>(x + (size_t)(bt0 + t) * DM + kq * 4);
        xs[(kq * 4 + 0) * BT + t] = v.x; xs[(kq * 4 + 1) * BT + t] = v.y;
        xs[(kq * 4 + 2) * BT + t] = v.z; xs[(kq * 4 + 3) * BT + t] = v.w;
    }
#pragma unroll
    for (int i = 0; i < 2; i++) {
        int idx = i * 128 + tid;
        int e = idx >> 2, kq = idx & 3;
        float4 v = *reinterpret_cast<const float4*>(W + (size_t)e * DM + kq * 4);
        *reinterpret_cast<float2*>(&ws[(kq * 4 + 0) * 128 + 2 * e]) = make_float2(v.x, v.x);
        *reinterpret_cast<float2*>(&ws[(kq * 4 + 1) * 128 + 2 * e]) = make_float2(v.y, v.y);
        *reinterpret_cast<float2*>(&ws[(kq * 4 + 2) * 128 + 2 * e]) = make_float2(v.z, v.z);
        *reinterpret_cast<float2*>(&ws[(kq * 4 + 3) * 128 + 2 * e]) = make_float2(v.w, v.w);
    }
    __syncthreads();

    // ---- main K loop, double buffered ----
    for (int kc = 0; kc < NCHUNK; kc++) {
        const int b = kc & 1;
        const float* xb_s = xs + b * (KB * BT);
        const float* wb_s = ws + b * (KB * 128);

        float4 px[4], pw[2];
        const bool more = (kc + 1 < NCHUNK);
        if (more) {
            const int k0 = (kc + 1) * KB;
#pragma unroll
            for (int i = 0; i < 4; i++) {
                int idx = i * 128 + tid;
                int t = idx >> 2, kq = idx & 3;
                px[i] = *reinterpret_cast<const float4*>(x + (size_t)(bt0 + t) * DM + k0 + kq * 4);
            }
#pragma unroll
            for (int i = 0; i < 2; i++) {
                int idx = i * 128 + tid;
                int e = idx >> 2, kq = idx & 3;
                pw[i] = *reinterpret_cast<const float4*>(W + (size_t)e * DM + k0 + kq * 4);
            }
        }

#pragma unroll
        for (int kk = 0; kk < KB; kk++) {
            const ulonglong2* xp = reinterpret_cast<const ulonglong2*>(xb_s + kk * BT + tg * 8);
            ulonglong2 xa = xp[0], xb2 = xp[1];
            uint64_t P[4] = {xa.x, xa.y, xb2.x, xb2.y};
            const ulonglong2* wp = reinterpret_cast<const ulonglong2*>(wb_s + kk * 128 + eg * 16);
            ulonglong2 w0 = wp[0], w1 = wp[1], w2 = wp[2], w3 = wp[3];
            uint64_t Wd[8] = {w0.x, w0.y, w1.x, w1.y, w2.x, w2.y, w3.x, w3.y};
#pragma unroll
            for (int p = 0; p < 4; p++)
#pragma unroll
                for (int j = 0; j < 8; j++)
                    FMA2(acc[p][j], P[p], Wd[j]);
        }

        if (more) {
            const int nb = b ^ 1;
            float* xn = xs + nb * (KB * BT);
            float* wn = ws + nb * (KB * 128);
#pragma unroll
            for (int i = 0; i < 4; i++) {
                int idx = i * 128 + tid;
                int t = idx >> 2, kq = idx & 3;
                xn[(kq * 4 + 0) * BT + t] = px[i].x; xn[(kq * 4 + 1) * BT + t] = px[i].y;
                xn[(kq * 4 + 2) * BT + t] = px[i].z; xn[(kq * 4 + 3) * BT + t] = px[i].w;
            }
#pragma unroll
            for (int i = 0; i < 2; i++) {
                int idx = i * 128 + tid;
                int e = idx >> 2, kq = idx & 3;
                *reinterpret_cast<float2*>(&wn[(kq * 4 + 0) * 128 + 2 * e]) = make_float2(pw[i].x, pw[i].x);
                *reinterpret_cast<float2*>(&wn[(kq * 4 + 1) * 128 + 2 * e]) = make_float2(pw[i].y, pw[i].y);
                *reinterpret_cast<float2*>(&wn[(kq * 4 + 2) * 128 + 2 * e]) = make_float2(pw[i].z, pw[i].z);
                *reinterpret_cast<float2*>(&wn[(kq * 4 + 3) * 128 + 2 * e]) = make_float2(pw[i].w, pw[i].w);
            }
        }
        __syncthreads();
    }

    // ---- dump accumulators to logits tile (unpack pairs) ----
#pragma unroll
    for (int p = 0; p < 4; p++) {
        float lo[8], hi[8];
#pragma unroll
        for (int j = 0; j < 8; j++) {
            lo[j] = __uint_as_float((uint32_t)acc[p][j]);
            hi[j] = __uint_as_float((uint32_t)(acc[p][j] >> 32));
        }
        float* r0 = ls + (size_t)(tg * 8 + 2 * p) * LSTR + eg * 8;
        float* r1 = r0 + LSTR;
        *reinterpret_cast<float4*>(r0)     = make_float4(lo[0], lo[1], lo[2], lo[3]);
        *reinterpret_cast<float4*>(r0 + 4) = make_float4(lo[4], lo[5], lo[6], lo[7]);
        *reinterpret_cast<float4*>(r1)     = make_float4(hi[0], hi[1], hi[2], hi[3]);
        *reinterpret_cast<float4*>(r1 + 4) = make_float4(hi[4], hi[5], hi[6], hi[7]);
    }
    __syncthreads();

    // ---- per-row epilogue: softmax + top2 + z (4 warps x 32 rows) ----
    const int warp = tid >> 5, lane = tid & 31;
    float zacc = 0.0f;

    for (int j = 0; j < 32; j++) {
        const int r = warp * 32 + j;
        const int token = bt0 + r;
        float a  = ls[(size_t)r * LSTR + lane];
        float bv = ls[(size_t)r * LSTR + lane + 32];
        zacc += a * a + bv * bv;

        float mx = fmaxf(a, bv);
#pragma unroll
        for (int off = 16; off; off >>= 1)
            mx = fmaxf(mx, __shfl_xor_sync(0xffffffffu, mx, off));

        float pa = expf(a - mx), pb = expf(bv - mx);
        float s = pa + pb;
#pragma unroll
        for (int off = 16; off; off >>= 1)
            s += __shfl_xor_sync(0xffffffffu, s, off);

        out_rw[(size_t)token * NE + lane]      = pa / s;
        out_rw[(size_t)token * NE + lane + 32] = pb / s;

        float v1, v2; int i1, i2;
        if (pa >= pb) { v1 = pa; i1 = lane;      v2 = pb; i2 = lane + 32; }
        else          { v1 = pb; i1 = lane + 32; v2 = pa; i2 = lane; }

#pragma unroll
        for (int off = 16; off; off >>= 1) {
            float o1 = __shfl_xor_sync(0xffffffffu, v1, off);
            int  oi1 = __shfl_xor_sync(0xffffffffu, i1, off);
            float o2 = __shfl_xor_sync(0xffffffffu, v2, off);
            int  oi2 = __shfl_xor_sync(0xffffffffu, i2, off);
            bool awins = (v1 > o1) || (v1 == o1 && i1 < oi1);
            if (awins) {
                bool keep = (v2 > o1) || (v2 == o1 && i2 < oi1);
                if (!keep) { v2 = o1; i2 = oi1; }
            } else {
                bool btwo = (o2 > v1) || (o2 == v1 && oi2 < i1);
                float nv2; int ni2;
                if (btwo) { nv2 = o2; ni2 = oi2; }
                else      { nv2 = v1; ni2 = i1; }
                v1 = o1; i1 = oi1; v2 = nv2; i2 = ni2;
            }
        }

        if (lane == 0) {
            float w1 = v1 / s, w2 = v2 / s;
            float sw = w1 + w2;
            g_e12[token] = i1 | (i2 << 8);
            g_w12[2 * token]     = w1 / (sw + 1e-8f);
            g_w12[2 * token + 1] = w2 / (sw + 1e-8f);
            atomicAdd(&g_cnt1[i1], 1);
        }
    }

#pragma unroll
    for (int off = 16; off; off >>= 1)
        zacc += __shfl_xor_sync(0xffffffffu, zacc, off);
    if (lane == 0) zred[warp] = zacc;
    __syncthreads();
    if (tid == 0)
        atomicAdd(&g_zsum, zred[0] + zred[1] + zred[2] + zred[3]);
}

// ---------------- stage B: dispatch mask + counts + (last block) loss + reset ----------------
#define NDBLK ((NTOK * 16) / 256)   // 1024

__global__ __launch_bounds__(256) void dispatch_loss_kernel(
    float* __restrict__ out_nd, float* __restrict__ out_loss)
{
    __shared__ int slast;

    const int gt = blockIdx.x * 256 + threadIdx.x;
    const int token = gt >> 4;
    const int c4 = gt & 15;

    const int e12 = g_e12[token];
    const int e1 = e12 & 0xff, e2 = (e12 >> 8) & 0xff;
    const float w1n = g_w12[2 * token];
    const float w2n = g_w12[2 * token + 1];
    const bool acc2 = (g_cnt1[e2] < CAP);
    const float den = w1n + (acc2 ? w2n : 0.0f) + 1e-8f;
    const float d1 = w1n / den;
    const float d2 = acc2 ? (w2n / den) : 0.0f;

    float4 v = make_float4(0.f, 0.f, 0.f, 0.f);
    const int c0 = c4 * 4;
    int r1 = e1 - c0;
    if (r1 == 0) v.x = d1; else if (r1 == 1) v.y = d1;
    else if (r1 == 2) v.z = d1; else if (r1 == 3) v.w = d1;
    int r2 = e2 - c0;
    if (r2 == 0) v.x = d2; else if (r2 == 1) v.y = d2;
    else if (r2 == 2) v.z = d2; else if (r2 == 3) v.w = d2;

    *reinterpret_cast<float4*>(out_nd + (size_t)token * NE + c0) = v;

    if (c4 == 0) {
        atomicAdd(&g_counts[e1], d1);
        if (acc2) atomicAdd(&g_counts[e2], d2);
    }

    // ---- last-block loss + scratch reset for next graph replay ----
    __threadfence();
    if (threadIdx.x == 0)
        slast = (atomicAdd(&g_done, 1) == NDBLK - 1);
    __syncthreads();

    if (slast) {
        const int t = threadIdx.x;
        if (t < 32) {
            const float invN = 1.0f / (float)NTOK;
            const float tgt = 512.0f / (float)NTOK;
            float d0 = g_counts[t] * invN - tgt;
            float dd1 = g_counts[t + 32] * invN - tgt;
            float s = d0 * d0 + dd1 * dd1;
#pragma unroll
            for (int off = 16; off; off >>= 1)
                s += __shfl_xor_sync(0xffffffffu, s, off);
            if (t == 0) {
                float lb = s / 64.0f;
                float z = g_zsum / (float)((size_t)NTOK * NE);
                out_loss[0] = 1e-3f * z + 1e-3f * lb;
            }
        }
        __syncthreads();
        if (t < NE) { g_cnt1[t] = 0; g_counts[t] = 0.0f; }
        if (t == 0) { g_zsum = 0.0f; g_done = 0; }
    }
}

// ---------------- launch ----------------
extern "C" void kernel_launch(void* const* d_in, const int* in_sizes, int n_in,
                              void* d_out, int out_size)
{
    const float* x = (const float*)d_in[0];
    const float* W = (const float*)d_in[1];
    if (n_in >= 2 && in_sizes[0] == NE * DM) {
        x = (const float*)d_in[1];
        W = (const float*)d_in[0];
    }
    float* out = (float*)d_out;

    gemm_router<<<NTOK / BT, 128, SMEM_FLOATS * sizeof(float)>>>(x, W, out);
    dispatch_loss_kernel<<<NDBLK, 256>>>(out + (size_t)NTOK * NE,
                                         out + (size_t)2 * NTOK * NE);
}

// round 9
// speedup vs baseline: 1.0105x; 1.0105x over previous
#include <cuda_runtime.h>
#include <math.h>
#include <stdint.h>

#define NTOK 16384
#define DM   2048
#define NE   64
#define CAP  640
#define BT   128
#define KB   32
#define NCHUNK (DM / KB)   // 64

// ---------------- device scratch (zero-initialized; reset by tail kernel) ----------------
__device__ int   g_e12[NTOK];
__device__ float g_w12[2 * NTOK];
__device__ int   g_cnt1[NE];
__device__ float g_counts[NE];
__device__ float g_zsum;
__device__ int   g_done;

// smem float offsets (dynamic)
#define XSOFF 0                      // [2][KB][BT] = 8192 floats
#define WSOFF (2 * KB * BT)          // [2][KB][64] = 4096 floats
#define LSTR  68                     // epilogue logits row stride
#define SMEM_FLOATS (2 * KB * BT + 2 * KB * 64)   // 12288 floats = 48 KB

// ---------------- stage A: fp32 GEMM 8x8 tile + fused epilogue ----------------
__global__ __launch_bounds__(128) void gemm_router(
    const float* __restrict__ x, const float* __restrict__ W,
    float* __restrict__ out_rw)
{
    extern __shared__ float sf[];
    float* xs = sf + XSOFF;
    float* ws = sf + WSOFF;
    float* ls = sf;                  // epilogue alias (8704 floats)
    __shared__ float zred[4];

    const int tid = threadIdx.x;
    const int tg  = tid & 15;        // 16 groups x 8 tokens
    const int eg  = tid >> 4;        // 8 groups x 8 experts
    const int bt0 = blockIdx.x * BT;

    float acc[8][8];
#pragma unroll
    for (int i = 0; i < 8; i++)
#pragma unroll
        for (int j = 0; j < 8; j++) acc[i][j] = 0.0f;

    // ---- load chunk 0 ----
#pragma unroll
    for (int i = 0; i < 8; i++) {
        int idx = i * 128 + tid;
        int t = idx >> 3, kq = idx & 7;
        float4 v = *reinterpret_cast<const float4*>(x + (size_t)(bt0 + t) * DM + kq * 4);
        xs[(kq * 4 + 0) * BT + t] = v.x; xs[(kq * 4 + 1) * BT + t] = v.y;
        xs[(kq * 4 + 2) * BT + t] = v.z; xs[(kq * 4 + 3) * BT + t] = v.w;
    }
#pragma unroll
    for (int i = 0; i < 4; i++) {
        int idx = i * 128 + tid;
        int e = idx >> 3, kq = idx & 7;
        float4 v = *reinterpret_cast<const float4*>(W + (size_t)e * DM + kq * 4);
        ws[(kq * 4 + 0) * 64 + e] = v.x; ws[(kq * 4 + 1) * 64 + e] = v.y;
        ws[(kq * 4 + 2) * 64 + e] = v.z; ws[(kq * 4 + 3) * 64 + e] = v.w;
    }
    __syncthreads();

    // ---- main K loop, double buffered ----
    for (int kc = 0; kc < NCHUNK; kc++) {
        const int b = kc & 1;
        const float* xb_s = xs + b * (KB * BT);
        const float* wb_s = ws + b * (KB * 64);

        float4 px[8], pw[4];
        const bool more = (kc + 1 < NCHUNK);
        if (more) {
            const int k0 = (kc + 1) * KB;
#pragma unroll
            for (int i = 0; i < 8; i++) {
                int idx = i * 128 + tid;
                int t = idx >> 3, kq = idx & 7;
                px[i] = *reinterpret_cast<const float4*>(x + (size_t)(bt0 + t) * DM + k0 + kq * 4);
            }
#pragma unroll
            for (int i = 0; i < 4; i++) {
                int idx = i * 128 + tid;
                int e = idx >> 3, kq = idx & 7;
                pw[i] = *reinterpret_cast<const float4*>(W + (size_t)e * DM + k0 + kq * 4);
            }
        }

#pragma unroll
        for (int kk = 0; kk < KB; kk++) {
            float4 xa  = *reinterpret_cast<const float4*>(xb_s + kk * BT + tg * 8);
            float4 xv2 = *reinterpret_cast<const float4*>(xb_s + kk * BT + tg * 8 + 4);
            float4 wa  = *reinterpret_cast<const float4*>(wb_s + kk * 64 + eg * 8);
            float4 wv2 = *reinterpret_cast<const float4*>(wb_s + kk * 64 + eg * 8 + 4);
            float xv[8] = {xa.x, xa.y, xa.z, xa.w, xv2.x, xv2.y, xv2.z, xv2.w};
            float wv[8] = {wa.x, wa.y, wa.z, wa.w, wv2.x, wv2.y, wv2.z, wv2.w};
#pragma unroll
            for (int i = 0; i < 8; i++)
#pragma unroll
                for (int j = 0; j < 8; j++)
                    acc[i][j] = fmaf(xv[i], wv[j], acc[i][j]);
        }

        if (more) {
            const int nb = b ^ 1;
            float* xn = xs + nb * (KB * BT);
            float* wn = ws + nb * (KB * 64);
#pragma unroll
            for (int i = 0; i < 8; i++) {
                int idx = i * 128 + tid;
                int t = idx >> 3, kq = idx & 7;
                xn[(kq * 4 + 0) * BT + t] = px[i].x; xn[(kq * 4 + 1) * BT + t] = px[i].y;
                xn[(kq * 4 + 2) * BT + t] = px[i].z; xn[(kq * 4 + 3) * BT + t] = px[i].w;
            }
#pragma unroll
            for (int i = 0; i < 4; i++) {
                int idx = i * 128 + tid;
                int e = idx >> 3, kq = idx & 7;
                wn[(kq * 4 + 0) * 64 + e] = pw[i].x; wn[(kq * 4 + 1) * 64 + e] = pw[i].y;
                wn[(kq * 4 + 2) * 64 + e] = pw[i].z; wn[(kq * 4 + 3) * 64 + e] = pw[i].w;
            }
        }
        __syncthreads();
    }

    // ---- dump accumulators to logits tile (aliases GEMM buffers) ----
#pragma unroll
    for (int i = 0; i < 8; i++) {
        float* row = ls + (size_t)(tg * 8 + i) * LSTR + eg * 8;
        *reinterpret_cast<float4*>(row)     = make_float4(acc[i][0], acc[i][1], acc[i][2], acc[i][3]);
        *reinterpret_cast<float4*>(row + 4) = make_float4(acc[i][4], acc[i][5], acc[i][6], acc[i][7]);
    }
    __syncthreads();

    // ---- per-row epilogue: softmax + top2 + z (4 warps x 32 rows) ----
    const int warp = tid >> 5, lane = tid & 31;
    float zacc = 0.0f;

    for (int j = 0; j < 32; j++) {
        const int r = warp * 32 + j;
        const int token = bt0 + r;
        float a  = ls[(size_t)r * LSTR + lane];
        float bv = ls[(size_t)r * LSTR + lane + 32];
        zacc += a * a + bv * bv;

        float mx = fmaxf(a, bv);
#pragma unroll
        for (int off = 16; off; off >>= 1)
            mx = fmaxf(mx, __shfl_xor_sync(0xffffffffu, mx, off));

        float pa = expf(a - mx), pb = expf(bv - mx);
        float s = pa + pb;
#pragma unroll
        for (int off = 16; off; off >>= 1)
            s += __shfl_xor_sync(0xffffffffu, s, off);

        out_rw[(size_t)token * NE + lane]      = pa / s;
        out_rw[(size_t)token * NE + lane + 32] = pb / s;

        float v1, v2; int i1, i2;
        if (pa >= pb) { v1 = pa; i1 = lane;      v2 = pb; i2 = lane + 32; }
        else          { v1 = pb; i1 = lane + 32; v2 = pa; i2 = lane; }

#pragma unroll
        for (int off = 16; off; off >>= 1) {
            float o1 = __shfl_xor_sync(0xffffffffu, v1, off);
            int  oi1 = __shfl_xor_sync(0xffffffffu, i1, off);
            float o2 = __shfl_xor_sync(0xffffffffu, v2, off);
            int  oi2 = __shfl_xor_sync(0xffffffffu, i2, off);
            bool awins = (v1 > o1) || (v1 == o1 && i1 < oi1);
            if (awins) {
                bool keep = (v2 > o1) || (v2 == o1 && i2 < oi1);
                if (!keep) { v2 = o1; i2 = oi1; }
            } else {
                bool btwo = (o2 > v1) || (o2 == v1 && oi2 < i1);
                float nv2; int ni2;
                if (btwo) { nv2 = o2; ni2 = oi2; }
                else      { nv2 = v1; ni2 = i1; }
                v1 = o1; i1 = oi1; v2 = nv2; i2 = ni2;
            }
        }

        if (lane == 0) {
            float w1 = v1 / s, w2 = v2 / s;
            float sw = w1 + w2;
            g_e12[token] = i1 | (i2 << 8);
            g_w12[2 * token]     = w1 / (sw + 1e-8f);
            g_w12[2 * token + 1] = w2 / (sw + 1e-8f);
            atomicAdd(&g_cnt1[i1], 1);
        }
    }

#pragma unroll
    for (int off = 16; off; off >>= 1)
        zacc += __shfl_xor_sync(0xffffffffu, zacc, off);
    if (lane == 0) zred[warp] = zacc;
    __syncthreads();
    if (tid == 0)
        atomicAdd(&g_zsum, zred[0] + zred[1] + zred[2] + zred[3]);
}

// ---------------- stage B: dispatch mask + counts + (last block) loss + reset ----------------
#define NDBLK ((NTOK * 16) / 256)   // 1024

__global__ __launch_bounds__(256) void dispatch_loss_kernel(
    float* __restrict__ out_nd, float* __restrict__ out_loss)
{
    __shared__ int slast;

    const int gt = blockIdx.x * 256 + threadIdx.x;
    const int token = gt >> 4;
    const int c4 = gt & 15;

    const int e12 = g_e12[token];
    const int e1 = e12 & 0xff, e2 = (e12 >> 8) & 0xff;
    const float w1n = g_w12[2 * token];
    const float w2n = g_w12[2 * token + 1];
    const bool acc2 = (g_cnt1[e2] < CAP);
    const float den = w1n + (acc2 ? w2n : 0.0f) + 1e-8f;
    const float d1 = w1n / den;
    const float d2 = acc2 ? (w2n / den) : 0.0f;

    float4 v = make_float4(0.f, 0.f, 0.f, 0.f);
    const int c0 = c4 * 4;
    int r1 = e1 - c0;
    if (r1 == 0) v.x = d1; else if (r1 == 1) v.y = d1;
    else if (r1 == 2) v.z = d1; else if (r1 == 3) v.w = d1;
    int r2 = e2 - c0;
    if (r2 == 0) v.x = d2; else if (r2 == 1) v.y = d2;
    else if (r2 == 2) v.z = d2; else if (r2 == 3) v.w = d2;

    *reinterpret_cast<float4*>(out_nd + (size_t)token * NE + c0) = v;

    if (c4 == 0) {
        atomicAdd(&g_counts[e1], d1);
        if (acc2) atomicAdd(&g_counts[e2], d2);
    }

    // ---- last-block loss + scratch reset for next graph replay ----
    __threadfence();
    if (threadIdx.x == 0)
        slast = (atomicAdd(&g_done, 1) == NDBLK - 1);
    __syncthreads();

    if (slast) {
        const int t = threadIdx.x;
        if (t < 32) {
            const float invN = 1.0f / (float)NTOK;
            const float tgt = 512.0f / (float)NTOK;
            float d0 = g_counts[t] * invN - tgt;
            float dd1 = g_counts[t + 32] * invN - tgt;
            float s = d0 * d0 + dd1 * dd1;
#pragma unroll
            for (int off = 16; off; off >>= 1)
                s += __shfl_xor_sync(0xffffffffu, s, off);
            if (t == 0) {
                float lb = s / 64.0f;
                float z = g_zsum / (float)((size_t)NTOK * NE);
                out_loss[0] = 1e-3f * z + 1e-3f * lb;
            }
        }
        __syncthreads();
        if (t < NE) { g_cnt1[t] = 0; g_counts[t] = 0.0f; }
        if (t == 0) { g_zsum = 0.0f; g_done = 0; }
    }
}

// ---------------- launch ----------------
extern "C" void kernel_launch(void* const* d_in, const int* in_sizes, int n_in,
                              void* d_out, int out_size)
{
    const float* x = (const float*)d_in[0];
    const float* W = (const float*)d_in[1];
    if (n_in >= 2 && in_sizes[0] == NE * DM) {
        x = (const float*)d_in[1];
        W = (const float*)d_in[0];
    }
    float* out = (float*)d_out;

    cudaFuncSetAttribute(gemm_router, cudaFuncAttributeMaxDynamicSharedMemorySize,
                         SMEM_FLOATS * sizeof(float));

    gemm_router<<<NTOK / BT, 128, SMEM_FLOATS * sizeof(float)>>>(x, W, out);
    dispatch_loss_kernel<<<NDBLK, 256>>>(out + (size_t)NTOK * NE,
                                         out + (size_t)2 * NTOK * NE);
}

// round 10
// speedup vs baseline: 1.5822x; 1.5658x over previous
#include <cuda_runtime.h>
#include <math.h>
#include <stdint.h>

#define NTOK 16384
#define DM   2048
#define NE   64
#define CAP  640
#define BT   128
#define KB   16
#define NSPLIT 8
#define KSL  (DM / NSPLIT)     // 256
#define NCHS (KSL / KB)        // 16 chunks per slice

// ---------------- device scratch ----------------
__device__ int   g_e12[NTOK];
__device__ float g_w12[2 * NTOK];
__device__ int   g_cnt1[NE];
__device__ float g_counts[NE];
__device__ float g_zsum;
__device__ float g_part[NSPLIT * NTOK * NE];   // 33.5 MB

// ---------------- stage A: K-split fp32 GEMM, 8x8 per-thread tile ----------------
__global__ __launch_bounds__(128) void gemm_partial(
    const float* __restrict__ x, const float* __restrict__ W)
{
    __shared__ __align__(16) float xs[2][KB][BT];   // 16 KB
    __shared__ __align__(16) float ws[2][KB][64];   // 8 KB

    const int tid = threadIdx.x;
    const int tg  = tid & 15;        // 16 groups x 8 tokens
    const int eg  = tid >> 4;        // 8 groups x 8 experts
    const int tt  = blockIdx.x & 127;
    const int ks  = blockIdx.x >> 7;
    const int bt0 = tt * BT;
    const int kbase = ks * KSL;

    if (blockIdx.x == 0 && tid < NE) {
        g_cnt1[tid] = 0; g_counts[tid] = 0.0f;
        if (tid == 0) g_zsum = 0.0f;
    }

    float acc[8][8];
#pragma unroll
    for (int i = 0; i < 8; i++)
#pragma unroll
        for (int j = 0; j < 8; j++) acc[i][j] = 0.0f;

    // ---- load chunk 0 ----
#pragma unroll
    for (int i = 0; i < 4; i++) {
        int idx = i * 128 + tid;
        int t = idx >> 2, kq = idx & 3;
        float4 v = *reinterpret_cast<const float4*>(x + (size_t)(bt0 + t) * DM + kbase + kq * 4);
        xs[0][kq * 4 + 0][t] = v.x; xs[0][kq * 4 + 1][t] = v.y;
        xs[0][kq * 4 + 2][t] = v.z; xs[0][kq * 4 + 3][t] = v.w;
    }
#pragma unroll
    for (int i = 0; i < 2; i++) {
        int idx = i * 128 + tid;
        int e = idx >> 2, kq = idx & 3;
        float4 v = *reinterpret_cast<const float4*>(W + (size_t)e * DM + kbase + kq * 4);
        ws[0][kq * 4 + 0][e] = v.x; ws[0][kq * 4 + 1][e] = v.y;
        ws[0][kq * 4 + 2][e] = v.z; ws[0][kq * 4 + 3][e] = v.w;
    }
    __syncthreads();

    // ---- main K loop, double buffered ----
    for (int kc = 0; kc < NCHS; kc++) {
        const int b = kc & 1;

        float4 px[4], pw[2];
        const bool more = (kc + 1 < NCHS);
        if (more) {
            const int k0 = kbase + (kc + 1) * KB;
#pragma unroll
            for (int i = 0; i < 4; i++) {
                int idx = i * 128 + tid;
                int t = idx >> 2, kq = idx & 3;
                px[i] = *reinterpret_cast<const float4*>(x + (size_t)(bt0 + t) * DM + k0 + kq * 4);
            }
#pragma unroll
            for (int i = 0; i < 2; i++) {
                int idx = i * 128 + tid;
                int e = idx >> 2, kq = idx & 3;
                pw[i] = *reinterpret_cast<const float4*>(W + (size_t)e * DM + k0 + kq * 4);
            }
        }

#pragma unroll
        for (int kk = 0; kk < KB; kk++) {
            float4 xa  = *reinterpret_cast<const float4*>(&xs[b][kk][tg * 8]);
            float4 xv2 = *reinterpret_cast<const float4*>(&xs[b][kk][tg * 8 + 4]);
            float4 wa  = *reinterpret_cast<const float4*>(&ws[b][kk][eg * 8]);
            float4 wv2 = *reinterpret_cast<const float4*>(&ws[b][kk][eg * 8 + 4]);
            float xv[8] = {xa.x, xa.y, xa.z, xa.w, xv2.x, xv2.y, xv2.z, xv2.w};
            float wv[8] = {wa.x, wa.y, wa.z, wa.w, wv2.x, wv2.y, wv2.z, wv2.w};
#pragma unroll
            for (int i = 0; i < 8; i++)
#pragma unroll
                for (int j = 0; j < 8; j++)
                    acc[i][j] = fmaf(xv[i], wv[j], acc[i][j]);
        }

        if (more) {
            const int nb = b ^ 1;
#pragma unroll
            for (int i = 0; i < 4; i++) {
                int idx = i * 128 + tid;
                int t = idx >> 2, kq = idx & 3;
                xs[nb][kq * 4 + 0][t] = px[i].x; xs[nb][kq * 4 + 1][t] = px[i].y;
                xs[nb][kq * 4 + 2][t] = px[i].z; xs[nb][kq * 4 + 3][t] = px[i].w;
            }
#pragma unroll
            for (int i = 0; i < 2; i++) {
                int idx = i * 128 + tid;
                int e = idx >> 2, kq = idx & 3;
                ws[nb][kq * 4 + 0][e] = pw[i].x; ws[nb][kq * 4 + 1][e] = pw[i].y;
                ws[nb][kq * 4 + 2][e] = pw[i].z; ws[nb][kq * 4 + 3][e] = pw[i].w;
            }
        }
        __syncthreads();
    }

    // ---- write partials ----
    float* pbase = g_part + ((size_t)ks * NTOK + bt0 + tg * 8) * NE + eg * 8;
#pragma unroll
    for (int i = 0; i < 8; i++) {
        float* row = pbase + (size_t)i * NE;
        *reinterpret_cast<float4*>(row)     = make_float4(acc[i][0], acc[i][1], acc[i][2], acc[i][3]);
        *reinterpret_cast<float4*>(row + 4) = make_float4(acc[i][4], acc[i][5], acc[i][6], acc[i][7]);
    }
}

// ---------------- stage B: reduce + softmax + top2 + z ----------------
__global__ __launch_bounds__(256) void reduce_kernel(float* __restrict__ out_rw)
{
    const int n = blockIdx.x * 256 + threadIdx.x;
    const int lane = threadIdx.x & 31;

    float L[64];
    const float* p0 = g_part + (size_t)n * NE;
#pragma unroll
    for (int q = 0; q < 16; q++) {
        float4 v = *reinterpret_cast<const float4*>(p0 + 4 * q);
        L[4 * q] = v.x; L[4 * q + 1] = v.y; L[4 * q + 2] = v.z; L[4 * q + 3] = v.w;
    }
#pragma unroll
    for (int s = 1; s < NSPLIT; s++) {
        const float* ps = g_part + ((size_t)s * NTOK + n) * NE;
#pragma unroll
        for (int q = 0; q < 16; q++) {
            float4 v = *reinterpret_cast<const float4*>(ps + 4 * q);
            L[4 * q] += v.x; L[4 * q + 1] += v.y; L[4 * q + 2] += v.z; L[4 * q + 3] += v.w;
        }
    }

    float zacc = 0.0f;
#pragma unroll
    for (int c = 0; c < 64; c++) zacc += L[c] * L[c];
#pragma unroll
    for (int off = 16; off; off >>= 1)
        zacc += __shfl_xor_sync(0xffffffffu, zacc, off);
    if (lane == 0) atomicAdd(&g_zsum, zacc);

    float mx = L[0];
#pragma unroll
    for (int c = 1; c < 64; c++) mx = fmaxf(mx, L[c]);
    float s = 0.0f;
#pragma unroll
    for (int c = 0; c < 64; c++) { L[c] = expf(L[c] - mx); s += L[c]; }
    const float inv = 1.0f / s;

    float* op = out_rw + (size_t)n * NE;
#pragma unroll
    for (int q = 0; q < 16; q++)
        *reinterpret_cast<float4*>(op + 4 * q) =
            make_float4(L[4 * q] * inv, L[4 * q + 1] * inv,
                        L[4 * q + 2] * inv, L[4 * q + 3] * inv);

    float v1 = -1.0f, v2 = -1.0f; int i1 = 0, i2 = 0;
#pragma unroll
    for (int c = 0; c < 64; c++) {
        const float pv = L[c];
        if (pv > v1)      { v2 = v1; i2 = i1; v1 = pv; i1 = c; }
        else if (pv > v2) { v2 = pv; i2 = c; }
    }
    const float w1 = v1 * inv, w2 = v2 * inv;
    const float den = w1 + w2 + 1e-8f;
    g_e12[n] = i1 | (i2 << 8);
    g_w12[2 * n]     = w1 / den;
    g_w12[2 * n + 1] = w2 / den;
    atomicAdd(&g_cnt1[i1], 1);
}

// ---------------- stage C: dispatch mask + normalized counts ----------------
__global__ __launch_bounds__(256) void dispatch_kernel(float* __restrict__ out_nd)
{
    const int gt = blockIdx.x * 256 + threadIdx.x;
    const int token = gt >> 4;
    const int c4 = gt & 15;
    if (token >= NTOK) return;

    const int e12 = g_e12[token];
    const int e1 = e12 & 0xff, e2 = (e12 >> 8) & 0xff;
    const float w1n = g_w12[2 * token];
    const float w2n = g_w12[2 * token + 1];
    const bool acc2 = (g_cnt1[e2] < CAP);
    const float den = w1n + (acc2 ? w2n : 0.0f) + 1e-8f;
    const float d1 = w1n / den;
    const float d2 = acc2 ? (w2n / den) : 0.0f;

    float4 v = make_float4(0.f, 0.f, 0.f, 0.f);
    const int c0 = c4 * 4;
    int r1 = e1 - c0;
    if (r1 == 0) v.x = d1; else if (r1 == 1) v.y = d1;
    else if (r1 == 2) v.z = d1; else if (r1 == 3) v.w = d1;
    int r2 = e2 - c0;
    if (r2 == 0) v.x = d2; else if (r2 == 1) v.y = d2;
    else if (r2 == 2) v.z = d2; else if (r2 == 3) v.w = d2;

    *reinterpret_cast<float4*>(out_nd + (size_t)token * NE + c0) = v;

    if (c4 == 0) {
        atomicAdd(&g_counts[e1], d1);
        if (acc2) atomicAdd(&g_counts[e2], d2);
    }
}

// ---------------- stage D: scalar loss ----------------
__global__ void loss_kernel(float* __restrict__ out)
{
    const int lane = threadIdx.x;
    const float invN = 1.0f / (float)NTOK;
    const float tgt = 512.0f / (float)NTOK;
    float d0 = g_counts[lane] * invN - tgt;
    float d1 = g_counts[lane + 32] * invN - tgt;
    float s = d0 * d0 + d1 * d1;
#pragma unroll
    for (int off = 16; off; off >>= 1)
        s += __shfl_xor_sync(0xffffffffu, s, off);
    if (lane == 0) {
        float lb = s / 64.0f;
        float z = g_zsum / (float)((size_t)NTOK * NE);
        out[(size_t)2 * NTOK * NE] = 1e-3f * z + 1e-3f * lb;
    }
}

// ---------------- launch ----------------
extern "C" void kernel_launch(void* const* d_in, const int* in_sizes, int n_in,
                              void* d_out, int out_size)
{
    const float* x = (const float*)d_in[0];
    const float* W = (const float*)d_in[1];
    if (n_in >= 2 && in_sizes[0] == NE * DM) {
        x = (const float*)d_in[1];
        W = (const float*)d_in[0];
    }
    float* out = (float*)d_out;

    gemm_partial<<<NSPLIT * 128, 128>>>(x, W);
    reduce_kernel<<<NTOK / 256, 256>>>(out);
    dispatch_kernel<<<(NTOK * 16) / 256, 256>>>(out + (size_t)NTOK * NE);
    loss_kernel<<<1, 32>>>(out);
}

// round 11
// speedup vs baseline: 1.6636x; 1.0514x over previous
#include <cuda_runtime.h>
#include <math.h>
#include <stdint.h>

#define NTOK 16384
#define DM   2048
#define NE   64
#define CAP  640
#define BT   128
#define KB   16
#define NSPLIT 8
#define KSL  (DM / NSPLIT)     // 256
#define NCHS (KSL / KB)        // 16

// ---------------- device scratch (zero-init; reset by loss tail / last-finisher) ----------------
__device__ int   g_e12[NTOK];
__device__ float g_w12[2 * NTOK];
__device__ int   g_cnt1[NE];
__device__ float g_counts[NE];
__device__ float g_zsum;
__device__ int   g_tilecnt[128];
__device__ float g_part[NSPLIT * NTOK * NE];   // 33.5 MB

// ---------------- stage A: K-split GEMM + last-finisher fused reduce/softmax/top2 ----------------
__global__ __launch_bounds__(128) void gemm_router(
    const float* __restrict__ x, const float* __restrict__ W,
    float* __restrict__ out_rw)
{
    __shared__ __align__(16) float xs[2][KB][BT];
    __shared__ __align__(16) float ws[2][KB][64];
    __shared__ int slast;

    const int tid = threadIdx.x;
    const int tg  = tid & 15;
    const int eg  = tid >> 4;
    const int tt  = blockIdx.x & 127;
    const int ks  = blockIdx.x >> 7;
    const int bt0 = tt * BT;
    const int kbase = ks * KSL;

    float acc[8][8];
#pragma unroll
    for (int i = 0; i < 8; i++)
#pragma unroll
        for (int j = 0; j < 8; j++) acc[i][j] = 0.0f;

    // ---- load chunk 0 ----
#pragma unroll
    for (int i = 0; i < 4; i++) {
        int idx = i * 128 + tid;
        int t = idx >> 2, kq = idx & 3;
        float4 v = *reinterpret_cast<const float4*>(x + (size_t)(bt0 + t) * DM + kbase + kq * 4);
        xs[0][kq * 4 + 0][t] = v.x; xs[0][kq * 4 + 1][t] = v.y;
        xs[0][kq * 4 + 2][t] = v.z; xs[0][kq * 4 + 3][t] = v.w;
    }
#pragma unroll
    for (int i = 0; i < 2; i++) {
        int idx = i * 128 + tid;
        int e = idx >> 2, kq = idx & 3;
        float4 v = *reinterpret_cast<const float4*>(W + (size_t)e * DM + kbase + kq * 4);
        ws[0][kq * 4 + 0][e] = v.x; ws[0][kq * 4 + 1][e] = v.y;
        ws[0][kq * 4 + 2][e] = v.z; ws[0][kq * 4 + 3][e] = v.w;
    }
    __syncthreads();

    for (int kc = 0; kc < NCHS; kc++) {
        const int b = kc & 1;
        float4 px[4], pw[2];
        const bool more = (kc + 1 < NCHS);
        if (more) {
            const int k0 = kbase + (kc + 1) * KB;
#pragma unroll
            for (int i = 0; i < 4; i++) {
                int idx = i * 128 + tid;
                int t = idx >> 2, kq = idx & 3;
                px[i] = *reinterpret_cast<const float4*>(x + (size_t)(bt0 + t) * DM + k0 + kq * 4);
            }
#pragma unroll
            for (int i = 0; i < 2; i++) {
                int idx = i * 128 + tid;
                int e = idx >> 2, kq = idx & 3;
                pw[i] = *reinterpret_cast<const float4*>(W + (size_t)e * DM + k0 + kq * 4);
            }
        }

#pragma unroll
        for (int kk = 0; kk < KB; kk++) {
            float4 xa  = *reinterpret_cast<const float4*>(&xs[b][kk][tg * 8]);
            float4 xv2 = *reinterpret_cast<const float4*>(&xs[b][kk][tg * 8 + 4]);
            float4 wa  = *reinterpret_cast<const float4*>(&ws[b][kk][eg * 8]);
            float4 wv2 = *reinterpret_cast<const float4*>(&ws[b][kk][eg * 8 + 4]);
            float xv[8] = {xa.x, xa.y, xa.z, xa.w, xv2.x, xv2.y, xv2.z, xv2.w};
            float wv[8] = {wa.x, wa.y, wa.z, wa.w, wv2.x, wv2.y, wv2.z, wv2.w};
#pragma unroll
            for (int i = 0; i < 8; i++)
#pragma unroll
                for (int j = 0; j < 8; j++)
                    acc[i][j] = fmaf(xv[i], wv[j], acc[i][j]);
        }

        if (more) {
            const int nb = b ^ 1;
#pragma unroll
            for (int i = 0; i < 4; i++) {
                int idx = i * 128 + tid;
                int t = idx >> 2, kq = idx & 3;
                xs[nb][kq * 4 + 0][t] = px[i].x; xs[nb][kq * 4 + 1][t] = px[i].y;
                xs[nb][kq * 4 + 2][t] = px[i].z; xs[nb][kq * 4 + 3][t] = px[i].w;
            }
#pragma unroll
            for (int i = 0; i < 2; i++) {
                int idx = i * 128 + tid;
                int e = idx >> 2, kq = idx & 3;
                ws[nb][kq * 4 + 0][e] = pw[i].x; ws[nb][kq * 4 + 1][e] = pw[i].y;
                ws[nb][kq * 4 + 2][e] = pw[i].z; ws[nb][kq * 4 + 3][e] = pw[i].w;
            }
        }
        __syncthreads();
    }

    // ---- write partials ----
    {
        float* pbase = g_part + ((size_t)ks * NTOK + bt0 + tg * 8) * NE + eg * 8;
#pragma unroll
        for (int i = 0; i < 8; i++) {
            float* row = pbase + (size_t)i * NE;
            *reinterpret_cast<float4*>(row)     = make_float4(acc[i][0], acc[i][1], acc[i][2], acc[i][3]);
            *reinterpret_cast<float4*>(row + 4) = make_float4(acc[i][4], acc[i][5], acc[i][6], acc[i][7]);
        }
    }

    // ---- completion counter (threadFenceReduction pattern) ----
    __threadfence();
    __syncthreads();
    if (tid == 0)
        slast = (atomicAdd(&g_tilecnt[tt], 1) == NSPLIT - 1);
    __syncthreads();
    if (!slast) return;

    // ---- last finisher: deterministic reduce (slices 0..7) + softmax + top2 + z ----
    const int n = bt0 + tid;     // one token per thread
    const int lane = tid & 31;

    float L[64];
    const float* p0 = g_part + (size_t)n * NE;
#pragma unroll
    for (int q = 0; q < 16; q++) {
        float4 v = *reinterpret_cast<const float4*>(p0 + 4 * q);
        L[4 * q] = v.x; L[4 * q + 1] = v.y; L[4 * q + 2] = v.z; L[4 * q + 3] = v.w;
    }
#pragma unroll
    for (int s = 1; s < NSPLIT; s++) {
        const float* ps = g_part + ((size_t)s * NTOK + n) * NE;
#pragma unroll
        for (int q = 0; q < 16; q++) {
            float4 v = *reinterpret_cast<const float4*>(ps + 4 * q);
            L[4 * q] += v.x; L[4 * q + 1] += v.y; L[4 * q + 2] += v.z; L[4 * q + 3] += v.w;
        }
    }

    float zacc = 0.0f;
#pragma unroll
    for (int c = 0; c < 64; c++) zacc += L[c] * L[c];
#pragma unroll
    for (int off = 16; off; off >>= 1)
        zacc += __shfl_xor_sync(0xffffffffu, zacc, off);
    if (lane == 0) atomicAdd(&g_zsum, zacc);

    float mx = L[0];
#pragma unroll
    for (int c = 1; c < 64; c++) mx = fmaxf(mx, L[c]);
    float s = 0.0f;
#pragma unroll
    for (int c = 0; c < 64; c++) { L[c] = expf(L[c] - mx); s += L[c]; }
    const float inv = 1.0f / s;

    float* op = out_rw + (size_t)n * NE;
#pragma unroll
    for (int q = 0; q < 16; q++)
        *reinterpret_cast<float4*>(op + 4 * q) =
            make_float4(L[4 * q] * inv, L[4 * q + 1] * inv,
                        L[4 * q + 2] * inv, L[4 * q + 3] * inv);

    float v1 = -1.0f, v2 = -1.0f; int i1 = 0, i2 = 0;
#pragma unroll
    for (int c = 0; c < 64; c++) {
        const float pv = L[c];
        if (pv > v1)      { v2 = v1; i2 = i1; v1 = pv; i1 = c; }
        else if (pv > v2) { v2 = pv; i2 = c; }
    }
    const float w1 = v1 * inv, w2 = v2 * inv;
    const float den = w1 + w2 + 1e-8f;
    g_e12[n] = i1 | (i2 << 8);
    g_w12[2 * n]     = w1 / den;
    g_w12[2 * n + 1] = w2 / den;
    atomicAdd(&g_cnt1[i1], 1);

    if (tid == 0) g_tilecnt[tt] = 0;   // reset for next graph replay
}

// ---------------- stage B: dispatch mask + normalized counts ----------------
__global__ __launch_bounds__(256) void dispatch_kernel(float* __restrict__ out_nd)
{
    const int gt = blockIdx.x * 256 + threadIdx.x;
    const int token = gt >> 4;
    const int c4 = gt & 15;
    if (token >= NTOK) return;

    const int e12 = g_e12[token];
    const int e1 = e12 & 0xff, e2 = (e12 >> 8) & 0xff;
    const float w1n = g_w12[2 * token];
    const float w2n = g_w12[2 * token + 1];
    const bool acc2 = (g_cnt1[e2] < CAP);
    const float den = w1n + (acc2 ? w2n : 0.0f) + 1e-8f;
    const float d1 = w1n / den;
    const float d2 = acc2 ? (w2n / den) : 0.0f;

    float4 v = make_float4(0.f, 0.f, 0.f, 0.f);
    const int c0 = c4 * 4;
    int r1 = e1 - c0;
    if (r1 == 0) v.x = d1; else if (r1 == 1) v.y = d1;
    else if (r1 == 2) v.z = d1; else if (r1 == 3) v.w = d1;
    int r2 = e2 - c0;
    if (r2 == 0) v.x = d2; else if (r2 == 1) v.y = d2;
    else if (r2 == 2) v.z = d2; else if (r2 == 3) v.w = d2;

    *reinterpret_cast<float4*>(out_nd + (size_t)token * NE + c0) = v;

    if (c4 == 0) {
        atomicAdd(&g_counts[e1], d1);
        if (acc2) atomicAdd(&g_counts[e2], d2);
    }
}

// ---------------- stage C: scalar loss + scratch reset for next replay ----------------
__global__ void loss_kernel(float* __restrict__ out)
{
    const int t = threadIdx.x;   // 64 threads
    if (t < 32) {
        const float invN = 1.0f / (float)NTOK;
        const float tgt = 512.0f / (float)NTOK;
        float d0 = g_counts[t] * invN - tgt;
        float d1 = g_counts[t + 32] * invN - tgt;
        float s = d0 * d0 + d1 * d1;
#pragma unroll
        for (int off = 16; off; off >>= 1)
            s += __shfl_xor_sync(0xffffffffu, s, off);
        if (t == 0) {
            float lb = s / 64.0f;
            float z = g_zsum / (float)((size_t)NTOK * NE);
            out[(size_t)2 * NTOK * NE] = 1e-3f * z + 1e-3f * lb;
        }
    }
    __syncthreads();
    // reset scratch for next graph replay (runs after all reads)
    g_cnt1[t] = 0; g_counts[t] = 0.0f;
    if (t == 0) g_zsum = 0.0f;
}

// ---------------- launch ----------------
extern "C" void kernel_launch(void* const* d_in, const int* in_sizes, int n_in,
                              void* d_out, int out_size)
{
    const float* x = (const float*)d_in[0];
    const float* W = (const float*)d_in[1];
    if (n_in >= 2 && in_sizes[0] == NE * DM) {
        x = (const float*)d_in[1];
        W = (const float*)d_in[0];
    }
    float* out = (float*)d_out;

    gemm_router<<<NSPLIT * 128, 128>>>(x, W, out);
    dispatch_kernel<<<(NTOK * 16) / 256, 256>>>(out + (size_t)NTOK * NE);
    loss_kernel<<<1, 64>>>(out);
}

// round 12
// speedup vs baseline: 1.8674x; 1.1225x over previous
#include <cuda_runtime.h>
#include <math.h>
#include <stdint.h>

#define NTOK 16384
#define DM   2048
#define NE   64
#define CAP  640
#define BT   128
#define KB   16
#define NSPLIT 8
#define KSL  (DM / NSPLIT)     // 256
#define NCHS (KSL / KB)        // 16

#define XSTR 148               // x smem row stride (floats)
#define WSTR 68                // w smem row stride (floats)
#define XCOL(t) ((t) + 4 * ((t) >> 5))   // bank-decorrelating column swizzle

// ---------------- device scratch (zero-init; reset in-kernel for replays) ----------------
__device__ int   g_e12[NTOK];
__device__ float g_w12[2 * NTOK];
__device__ int   g_cnt1[NE];
__device__ float g_counts[NE];
__device__ float g_zsum;
__device__ int   g_tilecnt[128];
__device__ float g_part[NSPLIT * NTOK * NE];   // 33.5 MB

// ---------------- stage A: K-split GEMM + last-finisher fused reduce/softmax/top2 ----------------
__global__ __launch_bounds__(128) void gemm_router(
    const float* __restrict__ x, const float* __restrict__ W,
    float* __restrict__ out_rw)
{
    __shared__ __align__(16) float xs[2 * KB * XSTR];   // 18.5 KB
    __shared__ __align__(16) float ws[2 * KB * WSTR];   // 8.5 KB
    __shared__ int slast;

    const int tid = threadIdx.x;
    const int tg  = tid & 15;
    const int eg  = tid >> 4;
    const int tt  = blockIdx.x & 127;
    const int ks  = blockIdx.x >> 7;
    const int bt0 = tt * BT;
    const int kbase = ks * KSL;
    const int xcol = tg * 8 + 4 * (tg >> 2);   // == XCOL(tg*8)

    float acc[8][8];
#pragma unroll
    for (int i = 0; i < 8; i++)
#pragma unroll
        for (int j = 0; j < 8; j++) acc[i][j] = 0.0f;

    // ---- load chunk 0 ----
#pragma unroll
    for (int i = 0; i < 4; i++) {
        int idx = i * 128 + tid;
        int t = idx >> 2, kq = idx & 3;
        float4 v = *reinterpret_cast<const float4*>(x + (size_t)(bt0 + t) * DM + kbase + kq * 4);
        const int c = XCOL(t);
        xs[(kq * 4 + 0) * XSTR + c] = v.x; xs[(kq * 4 + 1) * XSTR + c] = v.y;
        xs[(kq * 4 + 2) * XSTR + c] = v.z; xs[(kq * 4 + 3) * XSTR + c] = v.w;
    }
#pragma unroll
    for (int i = 0; i < 2; i++) {
        int idx = i * 128 + tid;
        int e = idx >> 2, kq = idx & 3;
        float4 v = *reinterpret_cast<const float4*>(W + (size_t)e * DM + kbase + kq * 4);
        ws[(kq * 4 + 0) * WSTR + e] = v.x; ws[(kq * 4 + 1) * WSTR + e] = v.y;
        ws[(kq * 4 + 2) * WSTR + e] = v.z; ws[(kq * 4 + 3) * WSTR + e] = v.w;
    }
    __syncthreads();

    for (int kc = 0; kc < NCHS; kc++) {
        const int b = kc & 1;
        const float* xb_s = xs + b * (KB * XSTR);
        const float* wb_s = ws + b * (KB * WSTR);

        float4 px[4], pw[2];
        const bool more = (kc + 1 < NCHS);
        if (more) {
            const int k0 = kbase + (kc + 1) * KB;
#pragma unroll
            for (int i = 0; i < 4; i++) {
                int idx = i * 128 + tid;
                int t = idx >> 2, kq = idx & 3;
                px[i] = *reinterpret_cast<const float4*>(x + (size_t)(bt0 + t) * DM + k0 + kq * 4);
            }
#pragma unroll
            for (int i = 0; i < 2; i++) {
                int idx = i * 128 + tid;
                int e = idx >> 2, kq = idx & 3;
                pw[i] = *reinterpret_cast<const float4*>(W + (size_t)e * DM + k0 + kq * 4);
            }
        }

#pragma unroll
        for (int kk = 0; kk < KB; kk++) {
            float4 xa  = *reinterpret_cast<const float4*>(xb_s + kk * XSTR + xcol);
            float4 xv2 = *reinterpret_cast<const float4*>(xb_s + kk * XSTR + xcol + 4);
            float4 wa  = *reinterpret_cast<const float4*>(wb_s + kk * WSTR + eg * 8);
            float4 wv2 = *reinterpret_cast<const float4*>(wb_s + kk * WSTR + eg * 8 + 4);
            float xv[8] = {xa.x, xa.y, xa.z, xa.w, xv2.x, xv2.y, xv2.z, xv2.w};
            float wv[8] = {wa.x, wa.y, wa.z, wa.w, wv2.x, wv2.y, wv2.z, wv2.w};
#pragma unroll
            for (int i = 0; i < 8; i++)
#pragma unroll
                for (int j = 0; j < 8; j++)
                    acc[i][j] = fmaf(xv[i], wv[j], acc[i][j]);
        }

        if (more) {
            const int nb = b ^ 1;
            float* xn = xs + nb * (KB * XSTR);
            float* wn = ws + nb * (KB * WSTR);
#pragma unroll
            for (int i = 0; i < 4; i++) {
                int idx = i * 128 + tid;
                int t = idx >> 2, kq = idx & 3;
                const int c = XCOL(t);
                xn[(kq * 4 + 0) * XSTR + c] = px[i].x; xn[(kq * 4 + 1) * XSTR + c] = px[i].y;
                xn[(kq * 4 + 2) * XSTR + c] = px[i].z; xn[(kq * 4 + 3) * XSTR + c] = px[i].w;
            }
#pragma unroll
            for (int i = 0; i < 2; i++) {
                int idx = i * 128 + tid;
                int e = idx >> 2, kq = idx & 3;
                wn[(kq * 4 + 0) * WSTR + e] = pw[i].x; wn[(kq * 4 + 1) * WSTR + e] = pw[i].y;
                wn[(kq * 4 + 2) * WSTR + e] = pw[i].z; wn[(kq * 4 + 3) * WSTR + e] = pw[i].w;
            }
        }
        __syncthreads();
    }

    // ---- write partials ----
    {
        float* pbase = g_part + ((size_t)ks * NTOK + bt0 + tg * 8) * NE + eg * 8;
#pragma unroll
        for (int i = 0; i < 8; i++) {
            float* row = pbase + (size_t)i * NE;
            *reinterpret_cast<float4*>(row)     = make_float4(acc[i][0], acc[i][1], acc[i][2], acc[i][3]);
            *reinterpret_cast<float4*>(row + 4) = make_float4(acc[i][4], acc[i][5], acc[i][6], acc[i][7]);
        }
    }

    // ---- completion counter ----
    __threadfence();
    __syncthreads();
    if (tid == 0)
        slast = (atomicAdd(&g_tilecnt[tt], 1) == NSPLIT - 1);
    __syncthreads();
    if (!slast) return;

    // ---- last finisher: deterministic reduce + softmax + top2 + z ----
    const int n = bt0 + tid;
    const int lane = tid & 31;

    float L[64];
    const float* p0 = g_part + (size_t)n * NE;
#pragma unroll
    for (int q = 0; q < 16; q++) {
        float4 v = *reinterpret_cast<const float4*>(p0 + 4 * q);
        L[4 * q] = v.x; L[4 * q + 1] = v.y; L[4 * q + 2] = v.z; L[4 * q + 3] = v.w;
    }
#pragma unroll
    for (int s = 1; s < NSPLIT; s++) {
        const float* ps = g_part + ((size_t)s * NTOK + n) * NE;
#pragma unroll
        for (int q = 0; q < 16; q++) {
            float4 v = *reinterpret_cast<const float4*>(ps + 4 * q);
            L[4 * q] += v.x; L[4 * q + 1] += v.y; L[4 * q + 2] += v.z; L[4 * q + 3] += v.w;
        }
    }

    float zacc = 0.0f;
#pragma unroll
    for (int c = 0; c < 64; c++) zacc += L[c] * L[c];
#pragma unroll
    for (int off = 16; off; off >>= 1)
        zacc += __shfl_xor_sync(0xffffffffu, zacc, off);
    if (lane == 0) atomicAdd(&g_zsum, zacc);

    float mx = L[0];
#pragma unroll
    for (int c = 1; c < 64; c++) mx = fmaxf(mx, L[c]);
    float s = 0.0f;
#pragma unroll
    for (int c = 0; c < 64; c++) { L[c] = expf(L[c] - mx); s += L[c]; }
    const float inv = 1.0f / s;

    float* op = out_rw + (size_t)n * NE;
#pragma unroll
    for (int q = 0; q < 16; q++)
        *reinterpret_cast<float4*>(op + 4 * q) =
            make_float4(L[4 * q] * inv, L[4 * q + 1] * inv,
                        L[4 * q + 2] * inv, L[4 * q + 3] * inv);

    float v1 = -1.0f, v2 = -1.0f; int i1 = 0, i2 = 0;
#pragma unroll
    for (int c = 0; c < 64; c++) {
        const float pv = L[c];
        if (pv > v1)      { v2 = v1; i2 = i1; v1 = pv; i1 = c; }
        else if (pv > v2) { v2 = pv; i2 = c; }
    }
    const float w1 = v1 * inv, w2 = v2 * inv;
    const float den = w1 + w2 + 1e-8f;
    g_e12[n] = i1 | (i2 << 8);
    g_w12[2 * n]     = w1 / den;
    g_w12[2 * n + 1] = w2 / den;
    atomicAdd(&g_cnt1[i1], 1);

    if (tid == 0) g_tilecnt[tt] = 0;
}

// ---------------- stage B: dispatch mask + normalized counts ----------------
__global__ __launch_bounds__(256) void dispatch_kernel(float* __restrict__ out_nd)
{
    const int gt = blockIdx.x * 256 + threadIdx.x;
    const int token = gt >> 4;
    const int c4 = gt & 15;
    if (token >= NTOK) return;

    const int e12 = g_e12[token];
    const int e1 = e12 & 0xff, e2 = (e12 >> 8) & 0xff;
    const float w1n = g_w12[2 * token];
    const float w2n = g_w12[2 * token + 1];
    const bool acc2 = (g_cnt1[e2] < CAP);
    const float den = w1n + (acc2 ? w2n : 0.0f) + 1e-8f;
    const float d1 = w1n / den;
    const float d2 = acc2 ? (w2n / den) : 0.0f;

    float4 v = make_float4(0.f, 0.f, 0.f, 0.f);
    const int c0 = c4 * 4;
    int r1 = e1 - c0;
    if (r1 == 0) v.x = d1; else if (r1 == 1) v.y = d1;
    else if (r1 == 2) v.z = d1; else if (r1 == 3) v.w = d1;
    int r2 = e2 - c0;
    if (r2 == 0) v.x = d2; else if (r2 == 1) v.y = d2;
    else if (r2 == 2) v.z = d2; else if (r2 == 3) v.w = d2;

    *reinterpret_cast<float4*>(out_nd + (size_t)token * NE + c0) = v;

    if (c4 == 0) {
        atomicAdd(&g_counts[e1], d1);
        if (acc2) atomicAdd(&g_counts[e2], d2);
    }
}

// ---------------- stage C: scalar loss + scratch reset ----------------
__global__ void loss_kernel(float* __restrict__ out)
{
    const int t = threadIdx.x;   // 64 threads
    if (t < 32) {
        const float invN = 1.0f / (float)NTOK;
        const float tgt = 512.0f / (float)NTOK;
        float d0 = g_counts[t] * invN - tgt;
        float d1 = g_counts[t + 32] * invN - tgt;
        float s = d0 * d0 + d1 * d1;
#pragma unroll
        for (int off = 16; off; off >>= 1)
            s += __shfl_xor_sync(0xffffffffu, s, off);
        if (t == 0) {
            float lb = s / 64.0f;
            float z = g_zsum / (float)((size_t)NTOK * NE);
            out[(size_t)2 * NTOK * NE] = 1e-3f * z + 1e-3f * lb;
        }
    }
    __syncthreads();
    g_cnt1[t] = 0; g_counts[t] = 0.0f;
    if (t == 0) g_zsum = 0.0f;
}

// ---------------- launch ----------------
extern "C" void kernel_launch(void* const* d_in, const int* in_sizes, int n_in,
                              void* d_out, int out_size)
{
    const float* x = (const float*)d_in[0];
    const float* W = (const float*)d_in[1];
    if (n_in >= 2 && in_sizes[0] == NE * DM) {
        x = (const float*)d_in[1];
        W = (const float*)d_in[0];
    }
    float* out = (float*)d_out;

    gemm_router<<<NSPLIT * 128, 128>>>(x, W, out);
    dispatch_kernel<<<(NTOK * 16) / 256, 256>>>(out + (size_t)NTOK * NE);
    loss_kernel<<<1, 64>>>(out);
}